// round 11
// baseline (speedup 1.0000x reference)
#include <cuda_runtime.h>
#include <cuda_fp16.h>
#include <cstdint>

#define T_TOK   262144
#define D_IN    128
#define D_H     256
#define D_OUT   128
#define N_SEG   8192
#define TILE_M  128
#define NTILES  (T_TOK / TILE_M)   // 2048
#define NCHUNK  4                  // D_H chunks of 64
#define GRID_M  1024               // 2 tiles per CTA

// ---------------- device scratch ----------------
__device__ uint32_t g_w1img[4][4096];   // [chunk] 16KB [k=128][n=64] swizzled fp16
__device__ uint32_t g_w2img[4][4096];   // [chunk] 2 panels [k=64][n=64] (8KB each)
__device__ int      g_segstart[N_SEG + 1];

// ---------------- SMEM layout (bytes) — all bases multiples of 512 ----------------
#define SM_SEG   0          // int[128]
#define SM_XS0   512        // x panel k0..63   [128 x 128B] SW128
#define SM_XS1   16896      // x panel k64..127
#define SM_W1A   33280      // w1 buf A (16KB, full chunk)
#define SM_W1B   49664      // w1 buf B
#define SM_W2A   66048      // w2 buf A (16KB, 2 panels)
#define SM_W2B   82432      // w2 buf B
#define SMEM_BYTES 98816    // +1KB sys -> x2 = 199680 <= 233472 -> occ 2
#define SM_OS    512        // fp16 h2 staging [128 x 256B] rotation-swizzled (= XS region)

__device__ __forceinline__ uint32_t sw(uint32_t b) { return b ^ ((b >> 3) & 0x70); }
// rotation swizzle for the 256B-row h2 staging: conflict-free stores and scans
__device__ __forceinline__ uint32_t os_addr(int r, int n2) {
    return (uint32_t)(SM_OS + r * 256 + ((n2 + ((r & 15) << 4)) & 255));
}

__device__ __forceinline__ uint32_t smem_u32(const void* p) {
    uint32_t a;
    asm("{ .reg .u64 t; cvta.to.shared.u64 t, %1; cvt.u32.u64 %0, t; }" : "=r"(a) : "l"(p));
    return a;
}
__device__ __forceinline__ void ldmA(uint32_t* a, uint32_t addr) {
    asm volatile("ldmatrix.sync.aligned.m8n8.x4.shared.b16 {%0,%1,%2,%3}, [%4];"
        : "=r"(a[0]), "=r"(a[1]), "=r"(a[2]), "=r"(a[3]) : "r"(addr));
}
__device__ __forceinline__ void ldmBT(uint32_t* b, uint32_t addr) {
    asm volatile("ldmatrix.sync.aligned.m8n8.x4.trans.shared.b16 {%0,%1,%2,%3}, [%4];"
        : "=r"(b[0]), "=r"(b[1]), "=r"(b[2]), "=r"(b[3]) : "r"(addr));
}
// fp32-accumulate fp16 MMA (layer 2)
__device__ __forceinline__ void mma_f16(float* c, const uint32_t* a, const uint32_t* b) {
    asm volatile(
        "mma.sync.aligned.m16n8k16.row.col.f32.f16.f16.f32 "
        "{%0,%1,%2,%3}, {%4,%5,%6,%7}, {%8,%9}, {%0,%1,%2,%3};"
        : "+f"(c[0]), "+f"(c[1]), "+f"(c[2]), "+f"(c[3])
        : "r"(a[0]), "r"(a[1]), "r"(a[2]), "r"(a[3]), "r"(b[0]), "r"(b[1]));
}
// fp16-accumulate fp16 MMA (layer 1)
__device__ __forceinline__ void mma_f16acc(uint32_t* c, const uint32_t* a, const uint32_t* b) {
    asm volatile(
        "mma.sync.aligned.m16n8k16.row.col.f16.f16.f16.f16 "
        "{%0,%1}, {%2,%3,%4,%5}, {%6,%7}, {%0,%1};"
        : "+r"(c[0]), "+r"(c[1])
        : "r"(a[0]), "r"(a[1]), "r"(a[2]), "r"(a[3]), "r"(b[0]), "r"(b[1]));
}
__device__ __forceinline__ void cpa16(uint32_t saddr, const void* g) {
    asm volatile("cp.async.cg.shared.global [%0], [%1], 16;" :: "r"(saddr), "l"(g));
}
#define CP_COMMIT() asm volatile("cp.async.commit_group;" ::: "memory")
#define CP_WAIT0()  asm volatile("cp.async.wait_group 0;" ::: "memory")

// ============================================================================
// Fused prep: weight images + segment bounds + output zeroing, one launch.
// w1[ch]: [k=128][n=64] 16KB: addr = k*128 + n*2 (SW128 per row)
// w2[ch]: panels p=0,1 [k=64][n=64]: addr = p*8192 + k*128 + n*2
// ============================================================================
__global__ void prep_all(const float* __restrict__ W1, const float* __restrict__ W2,
                         const int* __restrict__ seg, float* __restrict__ out)
{
    const int b = blockIdx.x;
    if (b < 128) {
        int idx = b * 256 + threadIdx.x;                 // 0..32767 words
        if (idx < 16384) {                               // w1
            int ch = idx >> 12, w = idx & 4095;
            uint32_t s = sw(w * 4);
            int k = s >> 7, nl = (s & 127) >> 1;
            __half2 v = __floats2half2_rn(W1[k * D_H + ch * 64 + nl],
                                          W1[k * D_H + ch * 64 + nl + 1]);
            g_w1img[ch][w] = *(uint32_t*)&v;
        } else {                                         // w2
            int i2 = idx - 16384;
            int ch = i2 >> 12, w = i2 & 4095;
            int p = w >> 11, wi = w & 2047;
            uint32_t s = sw(wi * 4);
            int kl = s >> 7, nl = (s & 127) >> 1;
            int k = ch * 64 + kl, n = p * 64 + nl;
            __half2 v = __floats2half2_rn(W2[k * D_OUT + n], W2[k * D_OUT + n + 1]);
            g_w2img[ch][w] = *(uint32_t*)&v;
        }
    } else if (b < 1152) {
        int i = (b - 128) * 256 + threadIdx.x;
        if (i >= T_TOK) return;
        int s  = seg[i];
        int sp = (i == 0) ? -1 : seg[i - 1];
        for (int t = sp + 1; t <= s; ++t) g_segstart[t] = i;
        if (i == T_TOK - 1)
            for (int t = s + 1; t <= N_SEG; ++t) g_segstart[t] = T_TOK;
    } else {
        int i = (b - 1152) * 256 + threadIdx.x;          // 0..262143 float4
        ((float4*)out)[i] = make_float4(0.f, 0.f, 0.f, 0.f);
    }
}

// ============================================================================
// Fused MLP + segment-mean. CTA = 2 tiles of 128 tokens, 8 warps x 16 rows
// each, FULL output width per warp. h1 never touches smem: layer-1 fp16
// accumulators are bias+ReLU'd in registers and consumed directly as layer-2
// A-fragments for all 4 k-steps. One __syncthreads per chunk (weight swap).
// ============================================================================
__global__ void __launch_bounds__(256, 2) mlp_kernel(
    const float* __restrict__ x, const int* __restrict__ seg,
    const float* __restrict__ b1, const float* __restrict__ b2,
    float* __restrict__ out)
{
    extern __shared__ char smem[];
    const uint32_t sbase = smem_u32(smem);
    const int tid = threadIdx.x, wid = tid >> 5, lane = tid & 31;
    const int l15 = lane & 15;
    const int colh = (lane >> 4) & 1;
    const int gr = lane >> 2, gc = lane & 3;

    int* segs = (int*)(smem + SM_SEG);

    // ---- initial weights: w1[0] -> W1A, w2[0] -> W2A ----
    {
        const uint4* s1 = (const uint4*)g_w1img[0];
        for (int i = tid; i < 1024; i += 256) cpa16(sbase + SM_W1A + i * 16, s1 + i);
        const uint4* s2 = (const uint4*)g_w2img[0];
        for (int i = tid; i < 1024; i += 256) cpa16(sbase + SM_W2A + i * 16, s2 + i);
        CP_COMMIT();
    }

    const uint32_t rA = (uint32_t)((wid * 16 + l15) * 128);   // A rows (16 per warp)

    #pragma unroll 1
    for (int tl = 0; tl < 2; ++tl) {
        const long tile0 = (long)(blockIdx.x + tl * GRID_M) * TILE_M;

        // ---- stage segs + x -> fp16 SW128 panels ----
        if (tid < TILE_M) segs[tid] = seg[tile0 + tid];
        {
            const float4* xg = (const float4*)(x + tile0 * D_IN);
            #pragma unroll 4
            for (int i = tid; i < TILE_M * D_IN / 4; i += 256) {
                float4 v = xg[i];
                int r = i >> 5, k0 = (i & 31) * 4;
                uint32_t pan = (k0 >= 64) ? SM_XS1 : SM_XS0;
                uint32_t a = sbase + pan + sw((uint32_t)(r * 128 + (k0 & 63) * 2));
                __half2 h0 = __floats2half2_rn(v.x, v.y);
                __half2 h1 = __floats2half2_rn(v.z, v.w);
                asm volatile("st.shared.v2.b32 [%0], {%1,%2};"
                    :: "r"(a), "r"(*(uint32_t*)&h0), "r"(*(uint32_t*)&h1) : "memory");
            }
        }

        float h2acc[16][4];   // [ntp*2+h][frag], cols ntp*16 + h*8 + gc*2 ..
        #pragma unroll
        for (int t = 0; t < 16; ++t)
            #pragma unroll
            for (int j = 0; j < 4; ++j) h2acc[t][j] = 0.f;

        #pragma unroll 1
        for (int ch = 0; ch < NCHUNK; ++ch) {
            const int p = ch & 1;
            const uint32_t w1cur = p ? SM_W1B : SM_W1A;
            const uint32_t w2cur = p ? SM_W2B : SM_W2A;

            CP_WAIT0();
            __syncthreads();   // chunk buffers + x landed; prev-buffer reads done

            // prefetch next chunk into the other buffers (wraps across tiles)
            if (tl == 0 || ch < 3) {
                const int chn = (ch + 1) & 3;
                const uint4* s1 = (const uint4*)g_w1img[chn];
                const uint32_t d1 = p ? SM_W1A : SM_W1B;
                #pragma unroll
                for (int i = tid; i < 1024; i += 256) cpa16(sbase + d1 + i * 16, s1 + i);
                const uint4* s2 = (const uint4*)g_w2img[chn];
                const uint32_t d2 = p ? SM_W2A : SM_W2B;
                #pragma unroll
                for (int i = tid; i < 1024; i += 256) cpa16(sbase + d2 + i * 16, s2 + i);
                CP_COMMIT();
            }

            // ---- layer 1 (fp16 acc): 16 rows x FULL chunk width (64 cols) ----
            uint32_t acc1[8][2];
            #pragma unroll
            for (int t = 0; t < 8; ++t) { acc1[t][0] = 0u; acc1[t][1] = 0u; }

            #pragma unroll
            for (int kt = 0; kt < 8; ++kt) {
                const uint32_t pan = (kt < 4) ? SM_XS0 : SM_XS1;
                const uint32_t kb = (kt & 3) * 32 + colh * 16;
                uint32_t a[4];
                ldmA(a, sbase + pan + sw(rA + kb));
                const uint32_t rB = (uint32_t)((kt * 16 + l15) * 128);
                #pragma unroll
                for (int ntp = 0; ntp < 4; ++ntp) {
                    uint32_t b[4];
                    ldmBT(b, sbase + w1cur + sw(rB + ntp * 32 + colh * 16));
                    mma_f16acc(acc1[ntp * 2],     a, b);
                    mma_f16acc(acc1[ntp * 2 + 1], a, b + 2);
                }
            }

            // ---- bias1 + ReLU in registers (acc1 = layer-2 A fragments) ----
            const __half2 z2 = __float2half2_rn(0.f);
            #pragma unroll
            for (int j = 0; j < 8; ++j) {
                const int n = (j >> 1) * 16 + (j & 1) * 8 + gc * 2;   // chunk-local
                const __half2 bb = __floats2half2_rn(__ldg(b1 + ch * 64 + n),
                                                     __ldg(b1 + ch * 64 + n + 1));
                __half2 v0 = __hmax2(__hadd2(*(__half2*)&acc1[j][0], bb), z2);
                __half2 v1 = __hmax2(__hadd2(*(__half2*)&acc1[j][1], bb), z2);
                acc1[j][0] = *(uint32_t*)&v0;
                acc1[j][1] = *(uint32_t*)&v1;
            }

            // ---- layer 2 (fp32 acc): ALL k register-chained, full 128 cols ----
            #pragma unroll
            for (int ktl = 0; ktl < 4; ++ktl) {
                uint32_t a[4] = { acc1[ktl * 2][0], acc1[ktl * 2][1],
                                  acc1[ktl * 2 + 1][0], acc1[ktl * 2 + 1][1] };
                const uint32_t rB = (uint32_t)((ktl * 16 + l15) * 128);
                #pragma unroll
                for (int ntp = 0; ntp < 8; ++ntp) {
                    uint32_t b[4];
                    ldmBT(b, sbase + w2cur + (uint32_t)(ntp >> 2) * 8192
                                  + sw(rB + (ntp & 3) * 32 + colh * 16));
                    mma_f16(h2acc[ntp * 2],     a, b);
                    mma_f16(h2acc[ntp * 2 + 1], a, b + 2);
                }
            }
        }
        __syncthreads();   // all XS reads done before OS overwrite

        // ---- epilogue 2: bias2 + ReLU -> fp16 rotation-swizzled staging ----
        #pragma unroll
        for (int ntp = 0; ntp < 8; ++ntp) {
            #pragma unroll
            for (int h = 0; h < 2; ++h) {
                const int j = ntp * 2 + h;
                const int n = ntp * 16 + h * 8 + gc * 2;
                const float bb0 = __ldg(b2 + n), bb1 = __ldg(b2 + n + 1);
                const int row0 = wid * 16 + gr;
                __half2 p0 = __floats2half2_rn(fmaxf(h2acc[j][0] + bb0, 0.f),
                                               fmaxf(h2acc[j][1] + bb1, 0.f));
                __half2 p1 = __floats2half2_rn(fmaxf(h2acc[j][2] + bb0, 0.f),
                                               fmaxf(h2acc[j][3] + bb1, 0.f));
                *(__half2*)(smem + os_addr(row0,     n * 2)) = p0;
                *(__half2*)(smem + os_addr(row0 + 8, n * 2)) = p1;
            }
        }
        __syncthreads();

        // ---- fused segment-mean: run scan, scale by 1/count, one atomic/run ----
        {
            const int c  = tid & 127;
            const int c2 = c * 2;
            const int rs = (tid >> 7) * 64;        // rows rs .. rs+63
            float acc = 0.f;
            int cur = segs[rs];
            #pragma unroll 4
            for (int r = rs; r < rs + 64; ++r) {
                acc += __half2float(*(const __half*)(smem + os_addr(r, c2)));
                const int nxt = (r + 1 < TILE_M) ? segs[r + 1] : -1;
                if (r == rs + 63 || nxt != cur) {
                    const int cnt = g_segstart[cur + 1] - g_segstart[cur];
                    atomicAdd(&out[cur * D_OUT + c], acc * __fdividef(1.f, (float)cnt));
                    acc = 0.f;
                    cur = nxt;
                }
            }
        }
        __syncthreads();   // OS region becomes XS again next tile
    }
}

// ============================================================================
extern "C" void kernel_launch(void* const* d_in, const int* in_sizes, int n_in,
                              void* d_out, int out_size)
{
    const float* x = nullptr; const int* sg = nullptr;
    const float* W1 = nullptr; const float* B1 = nullptr;
    const float* W2 = nullptr; const float* B2 = nullptr;
    int w_seen = 0;
    for (int i = 0; i < n_in; ++i) {
        const int sz = in_sizes[i];
        if (sz == T_TOK * D_IN)      x  = (const float*)d_in[i];
        else if (sz == T_TOK)        sg = (const int*)d_in[i];
        else if (sz == D_IN * D_H) { if (w_seen++ == 0) W1 = (const float*)d_in[i];
                                     else               W2 = (const float*)d_in[i]; }
        else if (sz == D_H)          B1 = (const float*)d_in[i];
        else if (sz == D_OUT)        B2 = (const float*)d_in[i];
    }

    cudaFuncSetAttribute(mlp_kernel, cudaFuncAttributeMaxDynamicSharedMemorySize, SMEM_BYTES);

    prep_all<<<2176, 256>>>(W1, W2, sg, (float*)d_out);
    mlp_kernel<<<GRID_M, 256, SMEM_BYTES>>>(x, sg, B1, B2, (float*)d_out);
}

// round 14
// speedup vs baseline: 1.1384x; 1.1384x over previous
#include <cuda_runtime.h>
#include <cuda_fp16.h>
#include <cstdint>

#define T_TOK   262144
#define D_IN    128
#define D_H     256
#define D_OUT   128
#define N_SEG   8192
#define TILE_M  128
#define NTILES  (T_TOK / TILE_M)   // 2048
#define NCHUNK  4                  // D_H chunks of 64
#define GRID_M  1024               // 2 tiles per CTA

// ---------------- device scratch ----------------
__device__ uint32_t g_w1img[4][2][2048];  // [chunk][ns] 8KB panels, [k=128][n=32] swizzled fp16
__device__ uint32_t g_w2img[4][4096];     // [chunk] 2 ns-panels [k=64][n=64] (8KB each)
__device__ int      g_segstart[N_SEG + 1];

// ---------------- SMEM layout (bytes) — all bases multiples of 512 ----------------
#define SM_SEG   0          // int[128]
#define SM_XS0   512        // x panel k0..63   [128 x 128B] SW128
#define SM_XS1   16896      // x panel k64..127
#define SM_W1A   33280      // w1 buf A: 2 ns-panels of 8KB
#define SM_W1B   49664      // w1 buf B
#define SM_W2A   66048      // w2 buf A: 2 ns-panels of 8KB
#define SM_W2B   82432      // w2 buf B
#define SM_H1    98816      // h1 chunk [128 x 128B]
#define SMEM_BYTES 115200   // occ 2
#define SM_OS    512        // fp16 h2 staging [128 x 256B] rotation-swizzled (XS region)

__device__ __forceinline__ uint32_t sw(uint32_t b) { return b ^ ((b >> 3) & 0x70); }
// rotation swizzle for the 256B-row h2 staging: conflict-free stores and scans
__device__ __forceinline__ uint32_t os_addr(int r, int n2) {
    return (uint32_t)(SM_OS + r * 256 + ((n2 + ((r & 15) << 4)) & 255));
}

__device__ __forceinline__ uint32_t smem_u32(const void* p) {
    uint32_t a;
    asm("{ .reg .u64 t; cvta.to.shared.u64 t, %1; cvt.u32.u64 %0, t; }" : "=r"(a) : "l"(p));
    return a;
}
__device__ __forceinline__ void ldmA(uint32_t* a, uint32_t addr) {
    asm volatile("ldmatrix.sync.aligned.m8n8.x4.shared.b16 {%0,%1,%2,%3}, [%4];"
        : "=r"(a[0]), "=r"(a[1]), "=r"(a[2]), "=r"(a[3]) : "r"(addr));
}
__device__ __forceinline__ void ldmBT(uint32_t* b, uint32_t addr) {
    asm volatile("ldmatrix.sync.aligned.m8n8.x4.trans.shared.b16 {%0,%1,%2,%3}, [%4];"
        : "=r"(b[0]), "=r"(b[1]), "=r"(b[2]), "=r"(b[3]) : "r"(addr));
}
// fp16-accumulate fp16 MMA (both layers; issue rate identical to fp32-acc, halves C regs)
__device__ __forceinline__ void mma_f16acc(uint32_t* c, const uint32_t* a, const uint32_t* b) {
    asm volatile(
        "mma.sync.aligned.m16n8k16.row.col.f16.f16.f16.f16 "
        "{%0,%1}, {%2,%3,%4,%5}, {%6,%7}, {%0,%1};"
        : "+r"(c[0]), "+r"(c[1])
        : "r"(a[0]), "r"(a[1]), "r"(a[2]), "r"(a[3]), "r"(b[0]), "r"(b[1]));
}
__device__ __forceinline__ void cpa16(uint32_t saddr, const void* g) {
    asm volatile("cp.async.cg.shared.global [%0], [%1], 16;" :: "r"(saddr), "l"(g));
}
#define CP_COMMIT() asm volatile("cp.async.commit_group;" ::: "memory")
#define CP_WAIT0()  asm volatile("cp.async.wait_group 0;" ::: "memory")
#define BAR(id, cnt) asm volatile("bar.sync %0, %1;" :: "r"(id), "r"(cnt) : "memory")

// ============================================================================
// Fused prep: weight images + segment bounds + output zeroing, one launch.
// w1[ch][ns]: [k=128][n=32] packed 64 rows x 128B: addr=(k&63)*128+(k>>6)*64+n*2
// w2[ch]: two ns-panels [k=64][n=64]: addr = k*128 + n*2
// ============================================================================
__global__ void prep_all(const float* __restrict__ W1, const float* __restrict__ W2,
                         const int* __restrict__ seg, float* __restrict__ out)
{
    const int b = blockIdx.x;
    if (b < 128) {
        const int idx = b * 256 + threadIdx.x;           // 0..32767 words
        if (idx < 16384) {                               // w1
            const int ch = idx >> 12, r = idx & 4095;
            const int ns = r >> 11, w = r & 2047;
            const uint32_t s = sw(w * 4);
            const int rowlow = s >> 7, inrow = s & 127;
            const int khigh = inrow >> 6, nl = (inrow & 63) >> 1;
            const int k = khigh * 64 + rowlow;
            const int n = ch * 64 + ns * 32 + nl;
            __half2 v = __floats2half2_rn(W1[k * D_H + n], W1[k * D_H + n + 1]);
            g_w1img[ch][ns][w] = *(uint32_t*)&v;
        } else {                                         // w2
            const int i2 = idx - 16384;
            const int ch = i2 >> 12, w = i2 & 4095;
            const int p = w >> 11, wi = w & 2047;
            const uint32_t s = sw(wi * 4);
            const int kl = s >> 7, nl = (s & 127) >> 1;
            const int k = ch * 64 + kl, n = p * 64 + nl;
            __half2 v = __floats2half2_rn(W2[k * D_OUT + n], W2[k * D_OUT + n + 1]);
            g_w2img[ch][w] = *(uint32_t*)&v;
        }
    } else if (b < 1152) {
        const int i = (b - 128) * 256 + threadIdx.x;
        if (i >= T_TOK) return;
        const int s  = seg[i];
        const int sp = (i == 0) ? -1 : seg[i - 1];
        for (int t = sp + 1; t <= s; ++t) g_segstart[t] = i;
        if (i == T_TOK - 1)
            for (int t = s + 1; t <= N_SEG; ++t) g_segstart[t] = T_TOK;
    } else {
        const int i = (b - 1152) * 256 + threadIdx.x;    // 0..262143 float4
        ((float4*)out)[i] = make_float4(0.f, 0.f, 0.f, 0.f);
    }
}

// ============================================================================
// Fused MLP + segment-mean. CTA = 2 tiles of 128 tokens, 4 m-groups x 2
// n-splits (traffic-optimal warp shape), occ 2. Layer-2 own-k-half register-
// chained from layer-1 fp16 accumulators; partner k-half via h1 smem. Both
// layers fp16-accumulate: h2acc = 32 regs, freeing ~30 regs of scheduling
// slack for ldmatrix pipelining under the 128-reg occ-2 cap.
// ============================================================================
__global__ void __launch_bounds__(256, 2) mlp_kernel(
    const float* __restrict__ x, const int* __restrict__ seg,
    const float* __restrict__ b1, const float* __restrict__ b2,
    float* __restrict__ out)
{
    extern __shared__ char smem[];
    const uint32_t sbase = smem_u32(smem);
    const int tid = threadIdx.x, wid = tid >> 5, lane = tid & 31;
    const int l15 = lane & 15;
    const int colh = (lane >> 4) & 1;
    const int gr = lane >> 2, gc = lane & 3;
    const int mg = wid & 3;            // m-group: rows mg*32 .. +31
    const int ns = wid >> 2;           // n-split half
    const int gtid = tid & 127;        // id within ns-group

    int* const segs = (int*)(smem + SM_SEG);

    // ---- initial weights: w1[0] -> W1A, w2[0] -> W2A ----
    {
        const uint4* const s1 = (const uint4*)g_w1img[0];
        const uint4* const s2 = (const uint4*)g_w2img[0];
        #pragma unroll 2
        for (int i = tid; i < 1024; i += 256) cpa16(sbase + SM_W1A + i * 16, s1 + i);
        #pragma unroll 2
        for (int i = tid; i < 1024; i += 256) cpa16(sbase + SM_W2A + i * 16, s2 + i);
        CP_COMMIT();
    }

    const uint32_t rA0 = (uint32_t)((mg * 32 + l15) * 128);        // mt0 A rows
    const uint32_t rA1 = (uint32_t)((mg * 32 + 16 + l15) * 128);   // mt1 A rows

    #pragma unroll 1
    for (int tl = 0; tl < 2; ++tl) {
        const long tile0 = (long)(blockIdx.x + tl * GRID_M) * TILE_M;

        // ---- stage segs + x -> fp16 SW128 panels ----
        if (tid < TILE_M) segs[tid] = seg[tile0 + tid];
        {
            const float4* const xg = (const float4*)(x + tile0 * D_IN);
            #pragma unroll 4
            for (int i = tid; i < TILE_M * D_IN / 4; i += 256) {
                const float4 v = xg[i];
                const int r = i >> 5, k0 = (i & 31) * 4;
                const uint32_t pan = (k0 >= 64) ? SM_XS1 : SM_XS0;
                const uint32_t a = sbase + pan + sw((uint32_t)(r * 128 + (k0 & 63) * 2));
                __half2 h0 = __floats2half2_rn(v.x, v.y);
                __half2 h1 = __floats2half2_rn(v.z, v.w);
                asm volatile("st.shared.v2.b32 [%0], {%1,%2};"
                    :: "r"(a), "r"(*(uint32_t*)&h0), "r"(*(uint32_t*)&h1) : "memory");
            }
        }
        __syncthreads();   // x + segs visible

        uint32_t h2acc[2][8][2];   // fp16 pairs: [mt][ntp*2+h][row-half]
        #pragma unroll
        for (int mt = 0; mt < 2; ++mt)
            #pragma unroll
            for (int t = 0; t < 8; ++t) { h2acc[mt][t][0] = 0u; h2acc[mt][t][1] = 0u; }

        #pragma unroll 1
        for (int ch = 0; ch < NCHUNK; ++ch) {
            const int p = ch & 1;
            const uint32_t w1cur = (p ? SM_W1B : SM_W1A) + (uint32_t)ns * 8192;
            const uint32_t w2cur = (p ? SM_W2B : SM_W2A) + (uint32_t)ns * 8192;

            CP_WAIT0();          // this chunk's buffers landed
            BAR(5 + ns, 128);    // group: mates landed + done reading other buffers

            // prefetch next chunk (wraps across the tile boundary; parity OK)
            if (tl == 0 || ch < 3) {
                const int chn = (ch + 1) & 3;
                const uint4* const s1 = (const uint4*)g_w1img[chn][ns];
                const uint4* const s2 = (const uint4*)g_w2img[chn] + ns * 512;
                const uint32_t d1 = (p ? SM_W1A : SM_W1B) + (uint32_t)ns * 8192;
                const uint32_t d2 = (p ? SM_W2A : SM_W2B) + (uint32_t)ns * 8192;
                #pragma unroll
                for (int i = gtid; i < 512; i += 128) cpa16(sbase + d1 + i * 16, s1 + i);
                #pragma unroll
                for (int i = gtid; i < 512; i += 128) cpa16(sbase + d2 + i * 16, s2 + i);
                CP_COMMIT();
            }

            // ---- layer 1 (fp16 acc): rows [mg*32,+32) x chunk cols [ns*32,+32)
            uint32_t acc1[2][4][2];
            #pragma unroll
            for (int mt = 0; mt < 2; ++mt)
                #pragma unroll
                for (int t = 0; t < 4; ++t) { acc1[mt][t][0] = 0u; acc1[mt][t][1] = 0u; }

            #pragma unroll
            for (int kt = 0; kt < 8; ++kt) {
                const uint32_t pan = (kt < 4) ? SM_XS0 : SM_XS1;
                const uint32_t kb = (kt & 3) * 32 + colh * 16;
                uint32_t a0[4], a1[4];
                ldmA(a0, sbase + pan + sw(rA0 + kb));
                ldmA(a1, sbase + pan + sw(rA1 + kb));
                const uint32_t rB = (uint32_t)((kt * 16 + l15) * 128);
                // w1 panel packs k>=64 rows at +64B: addr=(k&63)*128+(k>>6)*64
                const uint32_t rBw1 = (kt < 4) ? rB : (rB - 8192 + 64);
                #pragma unroll
                for (int ntp = 0; ntp < 2; ++ntp) {
                    uint32_t b[4];
                    ldmBT(b, sbase + w1cur + sw(rBw1 + ntp * 32 + colh * 16));
                    mma_f16acc(acc1[0][ntp * 2],     a0, b);
                    mma_f16acc(acc1[0][ntp * 2 + 1], a0, b + 2);
                    mma_f16acc(acc1[1][ntp * 2],     a1, b);
                    mma_f16acc(acc1[1][ntp * 2 + 1], a1, b + 2);
                }
            }

            // ---- bias1 + ReLU in registers (acc1 becomes h1 / layer-2 A frags)
            const __half2 z2 = __float2half2_rn(0.f);
            #pragma unroll
            for (int j = 0; j < 4; ++j) {
                const int n = ns * 32 + (j >> 1) * 16 + (j & 1) * 8 + gc * 2;
                const __half2 bb = __floats2half2_rn(__ldg(b1 + ch * 64 + n),
                                                     __ldg(b1 + ch * 64 + n + 1));
                #pragma unroll
                for (int mt = 0; mt < 2; ++mt) {
                    __half2 v0 = __hmax2(__hadd2(*(__half2*)&acc1[mt][j][0], bb), z2);
                    __half2 v1 = __hmax2(__hadd2(*(__half2*)&acc1[mt][j][1], bb), z2);
                    acc1[mt][j][0] = *(uint32_t*)&v0;
                    acc1[mt][j][1] = *(uint32_t*)&v1;
                }
            }

            BAR(1 + mg, 64);   // partner done reading my h1 half (prev chunk)

            // ---- store own h1 half for partner ----
            #pragma unroll
            for (int mt = 0; mt < 2; ++mt)
                #pragma unroll
                for (int j = 0; j < 4; ++j) {
                    const int n = ns * 32 + (j >> 1) * 16 + (j & 1) * 8 + gc * 2;
                    const int row0 = mg * 32 + mt * 16 + gr;
                    *(__half2*)(smem + SM_H1 + sw((uint32_t)(row0 * 128 + n * 2)))       = *(__half2*)&acc1[mt][j][0];
                    *(__half2*)(smem + SM_H1 + sw((uint32_t)((row0 + 8) * 128 + n * 2))) = *(__half2*)&acc1[mt][j][1];
                }

            // ---- layer 2 (fp16 acc), OWN k-half: A register-chained ----
            #pragma unroll
            for (int ktl = 0; ktl < 2; ++ktl) {
                const int kt = 2 * ns + ktl;
                uint32_t a0[4] = { acc1[0][ktl * 2][0], acc1[0][ktl * 2][1],
                                   acc1[0][ktl * 2 + 1][0], acc1[0][ktl * 2 + 1][1] };
                uint32_t a1[4] = { acc1[1][ktl * 2][0], acc1[1][ktl * 2][1],
                                   acc1[1][ktl * 2 + 1][0], acc1[1][ktl * 2 + 1][1] };
                const uint32_t rB = (uint32_t)((kt * 16 + l15) * 128);
                #pragma unroll
                for (int ntp = 0; ntp < 4; ++ntp) {
                    uint32_t b[4];
                    ldmBT(b, sbase + w2cur + sw(rB + ntp * 32 + colh * 16));
                    mma_f16acc(h2acc[0][ntp * 2],     a0, b);
                    mma_f16acc(h2acc[0][ntp * 2 + 1], a0, b + 2);
                    mma_f16acc(h2acc[1][ntp * 2],     a1, b);
                    mma_f16acc(h2acc[1][ntp * 2 + 1], a1, b + 2);
                }
            }

            BAR(1 + mg, 64);   // partner's h1 half written

            // ---- layer 2 (fp16 acc), PARTNER k-half: A from h1 smem ----
            #pragma unroll
            for (int ktl = 0; ktl < 2; ++ktl) {
                const int kt = 2 * (1 - ns) + ktl;
                const uint32_t kb = (uint32_t)(kt * 32) + colh * 16;
                uint32_t a0[4], a1[4];
                ldmA(a0, sbase + SM_H1 + sw(rA0 + kb));
                ldmA(a1, sbase + SM_H1 + sw(rA1 + kb));
                const uint32_t rB = (uint32_t)((kt * 16 + l15) * 128);
                #pragma unroll
                for (int ntp = 0; ntp < 4; ++ntp) {
                    uint32_t b[4];
                    ldmBT(b, sbase + w2cur + sw(rB + ntp * 32 + colh * 16));
                    mma_f16acc(h2acc[0][ntp * 2],     a0, b);
                    mma_f16acc(h2acc[0][ntp * 2 + 1], a0, b + 2);
                    mma_f16acc(h2acc[1][ntp * 2],     a1, b);
                    mma_f16acc(h2acc[1][ntp * 2 + 1], a1, b + 2);
                }
            }
        }
        __syncthreads();   // all XS/h1 reads done before OS overwrite

        // ---- epilogue 2: fp16 bias2 + ReLU -> rotation-swizzled staging ----
        {
            const __half2 z2 = __float2half2_rn(0.f);
            #pragma unroll
            for (int mt = 0; mt < 2; ++mt) {
                #pragma unroll
                for (int ntp = 0; ntp < 4; ++ntp) {
                    #pragma unroll
                    for (int h = 0; h < 2; ++h) {
                        const int j = ntp * 2 + h;
                        const int n = ns * 64 + ntp * 16 + h * 8 + gc * 2;
                        const __half2 bb = __floats2half2_rn(__ldg(b2 + n), __ldg(b2 + n + 1));
                        const int row0 = mg * 32 + mt * 16 + gr;
                        __half2 p0 = __hmax2(__hadd2(*(__half2*)&h2acc[mt][j][0], bb), z2);
                        __half2 p1 = __hmax2(__hadd2(*(__half2*)&h2acc[mt][j][1], bb), z2);
                        *(__half2*)(smem + os_addr(row0,     n * 2)) = p0;
                        *(__half2*)(smem + os_addr(row0 + 8, n * 2)) = p1;
                    }
                }
            }
        }
        __syncthreads();

        // ---- fused segment-mean: run scan, scale by 1/count, one atomic/run ----
        {
            const int c  = tid & 127;
            const int c2 = c * 2;
            const int rs = (tid >> 7) * 64;        // rows rs .. rs+63
            float acc = 0.f;
            int cur = segs[rs];
            #pragma unroll 4
            for (int r = rs; r < rs + 64; ++r) {
                acc += __half2float(*(const __half*)(smem + os_addr(r, c2)));
                const int nxt = (r + 1 < TILE_M) ? segs[r + 1] : -1;
                if (r == rs + 63 || nxt != cur) {
                    const int cnt = g_segstart[cur + 1] - g_segstart[cur];
                    atomicAdd(&out[cur * D_OUT + c], acc * __fdividef(1.f, (float)cnt));
                    acc = 0.f;
                    cur = nxt;
                }
            }
        }
        __syncthreads();   // OS region becomes XS again next tile
    }
}

// ============================================================================
extern "C" void kernel_launch(void* const* d_in, const int* in_sizes, int n_in,
                              void* d_out, int out_size)
{
    const float* x = nullptr; const int* sg = nullptr;
    const float* W1 = nullptr; const float* B1 = nullptr;
    const float* W2 = nullptr; const float* B2 = nullptr;
    int w_seen = 0;
    for (int i = 0; i < n_in; ++i) {
        const int sz = in_sizes[i];
        if (sz == T_TOK * D_IN)      x  = (const float*)d_in[i];
        else if (sz == T_TOK)        sg = (const int*)d_in[i];
        else if (sz == D_IN * D_H) { if (w_seen++ == 0) W1 = (const float*)d_in[i];
                                     else               W2 = (const float*)d_in[i]; }
        else if (sz == D_H)          B1 = (const float*)d_in[i];
        else if (sz == D_OUT)        B2 = (const float*)d_in[i];
    }

    cudaFuncSetAttribute(mlp_kernel, cudaFuncAttributeMaxDynamicSharedMemorySize, SMEM_BYTES);

    prep_all<<<2176, 256>>>(W1, W2, sg, (float*)d_out);
    mlp_kernel<<<GRID_M, 256, SMEM_BYTES>>>(x, sg, B1, B2, (float*)d_out);
}